// round 15
// baseline (speedup 1.0000x reference)
#include <cuda_runtime.h>

#define C_M 256
#define C_Z 128
#define NRES 768
#define SDIM 128
#define NBIN 15
#define LN_EPS 1e-5f

// block layout (256 threads = 8 warps everywhere)
#define CB 2368                      // copy blocks (grid-stride float4)
#define MB (NRES / 8)                // 96 m0 blocks, warp per row
#define ZB2 (NRES * NRES / 16)       // 36864 z blocks, warp per 2 (i,j) pairs

static __device__ __forceinline__ void warp_sum4(float& a, float& b, float& c, float& d) {
#pragma unroll
    for (int o = 16; o; o >>= 1) {
        a += __shfl_xor_sync(0xffffffffu, a, o);
        b += __shfl_xor_sync(0xffffffffu, b, o);
        c += __shfl_xor_sync(0xffffffffu, c, o);
        d += __shfl_xor_sync(0xffffffffu, d, o);
    }
}

static __device__ __forceinline__ void warp_sum2(float& a, float& b) {
#pragma unroll
    for (int o = 16; o; o >>= 1) {
        a += __shfl_xor_sync(0xffffffffu, a, o);
        b += __shfl_xor_sync(0xffffffffu, b, o);
    }
}

// ---------------------------------------------------------------------------
// Single fused kernel: phase A copy | phase B m0 LN-add | phase C z update
// ---------------------------------------------------------------------------
__global__ void __launch_bounds__(256)
fused_kernel(const float* __restrict__ m, const float* __restrict__ z,
             const float* __restrict__ mp, const float* __restrict__ zp,
             const float* __restrict__ x,
             const float* __restrict__ mw, const float* __restrict__ mb,
             const float* __restrict__ zw, const float* __restrict__ zb,
             const float* __restrict__ lw, const float* __restrict__ lb,
             float* __restrict__ out_m, float* __restrict__ out_z) {
    __shared__ float lw_s[C_Z * NBIN];   // 7680 B, raw copy of lw [C_Z][15]
    __shared__ float lb_s[C_Z];          // 512 B

    int b = blockIdx.x;
    int wid = threadIdx.x >> 5;
    int lane = threadIdx.x & 31;

    if (b < CB) {
        // Phase A: bulk copy of m rows s=1..S-1, 4-way unrolled for MLP
        const long long off4 = (long long)NRES * C_M / 4;
        const long long n4 = (long long)(SDIM - 1) * NRES * C_M / 4;
        const float4* src = ((const float4*)m) + off4;
        float4* dst = ((float4*)out_m) + off4;
        long long i = (long long)b * blockDim.x + threadIdx.x;
        const long long stride = (long long)CB * blockDim.x;
        for (; i + 3 * stride < n4; i += 4 * stride) {
            float4 v0 = __ldcs(src + i);
            float4 v1 = __ldcs(src + i + stride);
            float4 v2 = __ldcs(src + i + 2 * stride);
            float4 v3 = __ldcs(src + i + 3 * stride);
            __stcs(dst + i, v0);
            __stcs(dst + i + stride, v1);
            __stcs(dst + i + 2 * stride, v2);
            __stcs(dst + i + 3 * stride, v3);
        }
        for (; i < n4; i += stride) __stcs(dst + i, __ldcs(src + i));
        return;
    }

    if (b < CB + MB) {
        // Phase B: m[0,n,:] += LayerNorm(m_prev[0,n,:]) ; warp per row n
        int row = (b - CB) * 8 + wid;

        const float4* mp4 = (const float4*)(mp + (size_t)row * C_M);
        float4 a = mp4[lane];
        float4 c = mp4[lane + 32];

        float s  = a.x + a.y + a.z + a.w + c.x + c.y + c.z + c.w;
        float sq = a.x*a.x + a.y*a.y + a.z*a.z + a.w*a.w
                 + c.x*c.x + c.y*c.y + c.z*c.z + c.w*c.w;
        warp_sum2(s, sq);
        float mu = s * (1.0f / C_M);
        float var = sq * (1.0f / C_M) - mu * mu;
        float rstd = rsqrtf(fmaxf(var, 0.0f) + LN_EPS);

        const float4* w4p = (const float4*)mw;
        const float4* b4p = (const float4*)mb;
        const float4* m4 = (const float4*)(m + (size_t)row * C_M);
        float4* o4 = (float4*)(out_m + (size_t)row * C_M);

        float4 wa = w4p[lane], wb2 = w4p[lane + 32];
        float4 ba = b4p[lane], bb2 = b4p[lane + 32];
        float4 ma = m4[lane],  mb2 = m4[lane + 32];

        float4 r0, r1;
        r0.x = ma.x + (a.x - mu) * rstd * wa.x + ba.x;
        r0.y = ma.y + (a.y - mu) * rstd * wa.y + ba.y;
        r0.z = ma.z + (a.z - mu) * rstd * wa.z + ba.z;
        r0.w = ma.w + (a.w - mu) * rstd * wa.w + ba.w;
        r1.x = mb2.x + (c.x - mu) * rstd * wb2.x + bb2.x;
        r1.y = mb2.y + (c.y - mu) * rstd * wb2.y + bb2.y;
        r1.z = mb2.z + (c.z - mu) * rstd * wb2.z + bb2.z;
        r1.w = mb2.w + (c.w - mu) * rstd * wb2.w + bb2.w;
        o4[lane] = r0;
        o4[lane + 32] = r1;
        return;
    }

    // ------------------------------------------------------------------
    // Phase C: warp handles 2 consecutive pairs p0, p0+1 (rows contiguous)
    // z[p,:] = z + lb + lw[:,bin(p)] + LayerNorm(z_prev[p,:])
    // ------------------------------------------------------------------
    long long wp = (long long)(b - CB - MB) * 8 + wid;
    long long p0 = wp * 2;

    // issue the big streaming loads FIRST so smem fill hides under them
    size_t row = (size_t)p0 * C_Z;           // 64 float4 spanning both pairs
    const float4* zr  = (const float4*)(z  + row);
    const float4* zpr = (const float4*)(zp + row);
    float4 za  = __ldcs(zr  + lane);          // pair 0
    float4 zc  = __ldcs(zr  + lane + 32);     // pair 1
    float4 pa  = __ldcs(zpr + lane);
    float4 pc  = __ldcs(zpr + lane + 32);

    // raw coalesced copy of lw (1920 floats = 480 float4) and lb (32 float4)
    // into smem; lw/lb stay L1/L2-hot so this is ~2 vector ops per thread
    {
        const float4* lw4 = (const float4*)lw;
        float4* lws4 = (float4*)lw_s;
        for (int t = threadIdx.x; t < (C_Z * NBIN) / 4; t += 256)
            lws4[t] = __ldg(lw4 + t);
        const float4* lb4p = (const float4*)lb;
        float4* lbs4 = (float4*)lb_s;
        if (threadIdx.x < C_Z / 4)
            lbs4[threadIdx.x] = __ldg(lb4p + threadIdx.x);
    }

    // bin for pair (p0 + lane&1): even lanes pair0, odd lanes pair1
    int p = (int)p0 + (lane & 1);
    int i = p / NRES;
    int j = p - i * NRES;
    float dx = x[3 * i + 0] - x[3 * j + 0];
    float dy = x[3 * i + 1] - x[3 * j + 1];
    float dz = x[3 * i + 2] - x[3 * j + 2];
    float d = sqrtf(dx * dx + dy * dy + dz * dz);
    int bin = -1;  // -1 = no bin hit -> lb only (zero one-hot)
#pragma unroll
    for (int k = 0; k < NBIN; k++) {
        float bl = 3.25f + 1.25f * (float)k;
        float bu = (k < NBIN - 1) ? (bl + 1.25f) : 1e8f;
        if (d > bl && d < bu) bin = k;   // strict inequality, like reference
    }
    int bin0 = __shfl_sync(0xffffffffu, bin, 0);
    int bin1 = __shfl_sync(0xffffffffu, bin, 1);

    __syncthreads();   // smem tables ready (uniform path for phase-C blocks)

    // embedding for this lane's 4 channels, per pair (LDS, 4-way conflicts)
    int c0 = lane * 4;
    float4 lb4 = ((const float4*)lb_s)[lane];
    float e00 = lb4.x, e01 = lb4.y, e02 = lb4.z, e03 = lb4.w;
    float e10 = lb4.x, e11 = lb4.y, e12 = lb4.z, e13 = lb4.w;
    if (bin0 >= 0) {
        e00 += lw_s[(c0 + 0) * NBIN + bin0];
        e01 += lw_s[(c0 + 1) * NBIN + bin0];
        e02 += lw_s[(c0 + 2) * NBIN + bin0];
        e03 += lw_s[(c0 + 3) * NBIN + bin0];
    }
    if (bin1 >= 0) {
        e10 += lw_s[(c0 + 0) * NBIN + bin1];
        e11 += lw_s[(c0 + 1) * NBIN + bin1];
        e12 += lw_s[(c0 + 2) * NBIN + bin1];
        e13 += lw_s[(c0 + 3) * NBIN + bin1];
    }

    float s0 = pa.x + pa.y + pa.z + pa.w;
    float q0 = pa.x*pa.x + pa.y*pa.y + pa.z*pa.z + pa.w*pa.w;
    float s1 = pc.x + pc.y + pc.z + pc.w;
    float q1 = pc.x*pc.x + pc.y*pc.y + pc.z*pc.z + pc.w*pc.w;
    warp_sum4(s0, q0, s1, q1);
    float mu0 = s0 * (1.0f / C_Z);
    float mu1 = s1 * (1.0f / C_Z);
    float rs0 = rsqrtf(fmaxf(q0 * (1.0f / C_Z) - mu0 * mu0, 0.0f) + LN_EPS);
    float rs1 = rsqrtf(fmaxf(q1 * (1.0f / C_Z) - mu1 * mu1, 0.0f) + LN_EPS);

    float4 w4 = ((const float4*)zw)[lane];
    float4 b4 = ((const float4*)zb)[lane];
    float4* outr = (float4*)(out_z + row);

    float4 r;
    r.x = za.x + e00 + (pa.x - mu0) * rs0 * w4.x + b4.x;
    r.y = za.y + e01 + (pa.y - mu0) * rs0 * w4.y + b4.y;
    r.z = za.z + e02 + (pa.z - mu0) * rs0 * w4.z + b4.z;
    r.w = za.w + e03 + (pa.w - mu0) * rs0 * w4.w + b4.w;
    __stcs(outr + lane, r);

    float4 r2;
    r2.x = zc.x + e10 + (pc.x - mu1) * rs1 * w4.x + b4.x;
    r2.y = zc.y + e11 + (pc.y - mu1) * rs1 * w4.y + b4.y;
    r2.z = zc.z + e12 + (pc.z - mu1) * rs1 * w4.z + b4.z;
    r2.w = zc.w + e13 + (pc.w - mu1) * rs1 * w4.w + b4.w;
    __stcs(outr + lane + 32, r2);
}

extern "C" void kernel_launch(void* const* d_in, const int* in_sizes, int n_in,
                              void* d_out, int out_size) {
    const float* m      = (const float*)d_in[0];   // [S, N, C_M]
    const float* z      = (const float*)d_in[1];   // [N, N, C_Z]
    const float* m_prev = (const float*)d_in[2];   // [S, N, C_M]
    const float* z_prev = (const float*)d_in[3];   // [N, N, C_Z]
    const float* x_prev = (const float*)d_in[4];   // [N, 3]
    const float* ln_m_w = (const float*)d_in[5];
    const float* ln_m_b = (const float*)d_in[6];
    const float* ln_z_w = (const float*)d_in[7];
    const float* ln_z_b = (const float*)d_in[8];
    const float* lin_w  = (const float*)d_in[9];   // [C_Z, 15]
    const float* lin_b  = (const float*)d_in[10];  // [C_Z]

    float* out_m = (float*)d_out;
    float* out_z = out_m + (size_t)SDIM * NRES * C_M;   // m first, z second

    int blocks = CB + MB + ZB2;   // 2368 + 96 + 36864 = 39328
    fused_kernel<<<blocks, 256>>>(m, z, m_prev, z_prev, x_prev,
                                  ln_m_w, ln_m_b, ln_z_w, ln_z_b,
                                  lin_w, lin_b, out_m, out_z);
}

// round 17
// speedup vs baseline: 1.0778x; 1.0778x over previous
#include <cuda_runtime.h>

#define C_M 256
#define C_Z 128
#define NRES 768
#define SDIM 128
#define NBIN 15
#define LN_EPS 1e-5f

// block layout of the fused kernel (256 threads = 8 warps everywhere)
#define CB 2368                      // copy blocks (grid-stride float4)
#define MB (NRES / 8)                // 96 m0 blocks, warp per row
#define ZB2 (NRES * NRES / 16)       // 36864 z blocks, warp per 2 (i,j) pairs

// 8 KB embedding table: embT[bin][c] = lb[c] + lw[c*15+bin]; bin 15 = invalid
__device__ float g_embT[16 * C_Z];

static __device__ __forceinline__ void warp_sum4(float& a, float& b, float& c, float& d) {
#pragma unroll
    for (int o = 16; o; o >>= 1) {
        a += __shfl_xor_sync(0xffffffffu, a, o);
        b += __shfl_xor_sync(0xffffffffu, b, o);
        c += __shfl_xor_sync(0xffffffffu, c, o);
        d += __shfl_xor_sync(0xffffffffu, d, o);
    }
}

static __device__ __forceinline__ void warp_sum2(float& a, float& b) {
#pragma unroll
    for (int o = 16; o; o >>= 1) {
        a += __shfl_xor_sync(0xffffffffu, a, o);
        b += __shfl_xor_sync(0xffffffffu, b, o);
    }
}

// ---------------------------------------------------------------------------
// Prep kernel (1 block): embT[bin][c] = lb[c] + lw[c*15+bin] (bin 15 -> lb)
// ---------------------------------------------------------------------------
__global__ void __launch_bounds__(256)
prep_kernel(const float* __restrict__ lw, const float* __restrict__ lb) {
    for (int idx = threadIdx.x; idx < 16 * C_Z; idx += 256) {
        int bin = idx >> 7;          // 0..15
        int c = idx & (C_Z - 1);
        float v = lb[c];
        if (bin < NBIN) v += lw[c * NBIN + bin];
        g_embT[bin * C_Z + c] = v;
    }
}

// ---------------------------------------------------------------------------
// Fused main kernel: phase A copy | phase B m0 LN-add | phase C z update
// ---------------------------------------------------------------------------
__global__ void __launch_bounds__(256)
fused_kernel(const float* __restrict__ m, const float* __restrict__ z,
             const float* __restrict__ mp, const float* __restrict__ zp,
             const float* __restrict__ x,
             const float* __restrict__ mw, const float* __restrict__ mb,
             const float* __restrict__ zw, const float* __restrict__ zb,
             float* __restrict__ out_m, float* __restrict__ out_z) {
    int b = blockIdx.x;
    int wid = threadIdx.x >> 5;
    int lane = threadIdx.x & 31;

    if (b < CB) {
        // Phase A: bulk copy of m rows s=1..S-1, 4-way unrolled for MLP
        const long long off4 = (long long)NRES * C_M / 4;
        const long long n4 = (long long)(SDIM - 1) * NRES * C_M / 4;
        const float4* src = ((const float4*)m) + off4;
        float4* dst = ((float4*)out_m) + off4;
        long long i = (long long)b * blockDim.x + threadIdx.x;
        const long long stride = (long long)CB * blockDim.x;
        for (; i + 3 * stride < n4; i += 4 * stride) {
            float4 v0 = __ldcs(src + i);
            float4 v1 = __ldcs(src + i + stride);
            float4 v2 = __ldcs(src + i + 2 * stride);
            float4 v3 = __ldcs(src + i + 3 * stride);
            __stcs(dst + i, v0);
            __stcs(dst + i + stride, v1);
            __stcs(dst + i + 2 * stride, v2);
            __stcs(dst + i + 3 * stride, v3);
        }
        for (; i < n4; i += stride) __stcs(dst + i, __ldcs(src + i));
        return;
    }

    if (b < CB + MB) {
        // Phase B: m[0,n,:] += LayerNorm(m_prev[0,n,:]) ; warp per row n
        int row = (b - CB) * 8 + wid;

        const float4* mp4 = (const float4*)(mp + (size_t)row * C_M);
        float4 a = mp4[lane];
        float4 c = mp4[lane + 32];

        float s  = a.x + a.y + a.z + a.w + c.x + c.y + c.z + c.w;
        float sq = a.x*a.x + a.y*a.y + a.z*a.z + a.w*a.w
                 + c.x*c.x + c.y*c.y + c.z*c.z + c.w*c.w;
        warp_sum2(s, sq);
        float mu = s * (1.0f / C_M);
        float var = sq * (1.0f / C_M) - mu * mu;
        float rstd = rsqrtf(fmaxf(var, 0.0f) + LN_EPS);

        const float4* w4p = (const float4*)mw;
        const float4* b4p = (const float4*)mb;
        const float4* m4 = (const float4*)(m + (size_t)row * C_M);
        float4* o4 = (float4*)(out_m + (size_t)row * C_M);

        float4 wa = w4p[lane], wb2 = w4p[lane + 32];
        float4 ba = b4p[lane], bb2 = b4p[lane + 32];
        float4 ma = m4[lane],  mb2 = m4[lane + 32];

        float4 r0, r1;
        r0.x = ma.x + (a.x - mu) * rstd * wa.x + ba.x;
        r0.y = ma.y + (a.y - mu) * rstd * wa.y + ba.y;
        r0.z = ma.z + (a.z - mu) * rstd * wa.z + ba.z;
        r0.w = ma.w + (a.w - mu) * rstd * wa.w + ba.w;
        r1.x = mb2.x + (c.x - mu) * rstd * wb2.x + bb2.x;
        r1.y = mb2.y + (c.y - mu) * rstd * wb2.y + bb2.y;
        r1.z = mb2.z + (c.z - mu) * rstd * wb2.z + bb2.z;
        r1.w = mb2.w + (c.w - mu) * rstd * wb2.w + bb2.w;
        o4[lane] = r0;
        o4[lane + 32] = r1;
        return;
    }

    // ------------------------------------------------------------------
    // Phase C: warp handles 2 consecutive pairs p0, p0+1 (rows contiguous)
    // z[p,:] = z + embT[bin(p)] + LayerNorm(z_prev[p,:])
    // ------------------------------------------------------------------
    long long wp = (long long)(b - CB - MB) * 8 + wid;
    long long p0 = wp * 2;

    size_t row = (size_t)p0 * C_Z;           // 64 float4 spanning both pairs
    const float4* zr  = (const float4*)(z  + row);
    const float4* zpr = (const float4*)(zp + row);
    float4 za  = __ldcs(zr  + lane);          // pair 0
    float4 zc  = __ldcs(zr  + lane + 32);     // pair 1
    float4 pa  = __ldcs(zpr + lane);
    float4 pc  = __ldcs(zpr + lane + 32);

    // bin for pair (p0 + lane&1): even lanes pair0, odd lanes pair1
    int p = (int)p0 + (lane & 1);
    int i = p / NRES;
    int j = p - i * NRES;
    float dx = x[3 * i + 0] - x[3 * j + 0];
    float dy = x[3 * i + 1] - x[3 * j + 1];
    float dz = x[3 * i + 2] - x[3 * j + 2];
    float d = sqrtf(dx * dx + dy * dy + dz * dz);
    int bin = 15;  // 15 = no bin hit -> lb only (zero one-hot)
#pragma unroll
    for (int k = 0; k < NBIN; k++) {
        float bl = 3.25f + 1.25f * (float)k;
        float bu = (k < NBIN - 1) ? (bl + 1.25f) : 1e8f;
        if (d > bl && d < bu) bin = k;   // strict inequality, like reference
    }
    int bin0 = __shfl_sync(0xffffffffu, bin, 0);
    int bin1 = __shfl_sync(0xffffffffu, bin, 1);

    float4 e0 = ((const float4*)(g_embT + bin0 * C_Z))[lane];
    float4 e1 = ((const float4*)(g_embT + bin1 * C_Z))[lane];

    float s0 = pa.x + pa.y + pa.z + pa.w;
    float q0 = pa.x*pa.x + pa.y*pa.y + pa.z*pa.z + pa.w*pa.w;
    float s1 = pc.x + pc.y + pc.z + pc.w;
    float q1 = pc.x*pc.x + pc.y*pc.y + pc.z*pc.z + pc.w*pc.w;
    warp_sum4(s0, q0, s1, q1);
    float mu0 = s0 * (1.0f / C_Z);
    float mu1 = s1 * (1.0f / C_Z);
    float rs0 = rsqrtf(fmaxf(q0 * (1.0f / C_Z) - mu0 * mu0, 0.0f) + LN_EPS);
    float rs1 = rsqrtf(fmaxf(q1 * (1.0f / C_Z) - mu1 * mu1, 0.0f) + LN_EPS);

    float4 w4 = ((const float4*)zw)[lane];
    float4 b4 = ((const float4*)zb)[lane];
    float4* outr = (float4*)(out_z + row);

    float4 r;
    r.x = za.x + e0.x + (pa.x - mu0) * rs0 * w4.x + b4.x;
    r.y = za.y + e0.y + (pa.y - mu0) * rs0 * w4.y + b4.y;
    r.z = za.z + e0.z + (pa.z - mu0) * rs0 * w4.z + b4.z;
    r.w = za.w + e0.w + (pa.w - mu0) * rs0 * w4.w + b4.w;
    __stcs(outr + lane, r);

    float4 r2;
    r2.x = zc.x + e1.x + (pc.x - mu1) * rs1 * w4.x + b4.x;
    r2.y = zc.y + e1.y + (pc.y - mu1) * rs1 * w4.y + b4.y;
    r2.z = zc.z + e1.z + (pc.z - mu1) * rs1 * w4.z + b4.z;
    r2.w = zc.w + e1.w + (pc.w - mu1) * rs1 * w4.w + b4.w;
    __stcs(outr + lane + 32, r2);
}

extern "C" void kernel_launch(void* const* d_in, const int* in_sizes, int n_in,
                              void* d_out, int out_size) {
    const float* m      = (const float*)d_in[0];   // [S, N, C_M]
    const float* z      = (const float*)d_in[1];   // [N, N, C_Z]
    const float* m_prev = (const float*)d_in[2];   // [S, N, C_M]
    const float* z_prev = (const float*)d_in[3];   // [N, N, C_Z]
    const float* x_prev = (const float*)d_in[4];   // [N, 3]
    const float* ln_m_w = (const float*)d_in[5];
    const float* ln_m_b = (const float*)d_in[6];
    const float* ln_z_w = (const float*)d_in[7];
    const float* ln_z_b = (const float*)d_in[8];
    const float* lin_w  = (const float*)d_in[9];   // [C_Z, 15]
    const float* lin_b  = (const float*)d_in[10];  // [C_Z]

    float* out_m = (float*)d_out;
    float* out_z = out_m + (size_t)SDIM * NRES * C_M;   // m first, z second

    prep_kernel<<<1, 256>>>(lin_w, lin_b);

    int blocks = CB + MB + ZB2;   // 2368 + 96 + 36864 = 39328
    fused_kernel<<<blocks, 256>>>(m, z, m_prev, z_prev, x_prev,
                                  ln_m_w, ln_m_b, ln_z_w, ln_z_b,
                                  out_m, out_z);
}